// round 9
// baseline (speedup 1.0000x reference)
#include <cuda_runtime.h>
#include <cuda_bf16.h>

// Shapes (fixed by the problem)
#define B_   32
#define D_   512
#define HID_ 256
#define NF_  8
#define CIN_ 64
#define COUT_ 64
#define HW_  64

// Conv tiling: block = 16 oc x (32 wide x 16 tall) tile, 256 threads, 2 CTAs/SM
#define OG_    16   // output channels per block
#define TW_    32   // tile width
#define TH_    16   // tile height
#define CC_    4    // cin chunk per stage (double buffered)
#define NCHUNK (CIN_ / CC_)          // 16
#define ISTR2_ 72   // duplicated input row stride in floats (34 dup-pairs = 68 used)
#define WSTR_  16   // weight smem row stride (16 oc, taps 16B-aligned)

#define W_S_FLOATS   (CIN_ * 9 * WSTR_)          // 9216
#define IN_BUF_FLOATS (CC_ * 18 * ISTR2_)        // 5184
#define SMEM_FLOATS  (W_S_FLOATS + 2 * IN_BUF_FLOATS)  // 19584 -> 78336 B

// -------- device scratch (no allocations allowed) --------
__device__ float g_attn[B_ * NF_];
__device__ float g_h[B_ * HID_];
__device__ float g_aggw[B_ * COUT_ * CIN_ * 9];  // [b][oc][ci][tap], 4.7 MB

// -------- packed fp32x2 FMA (sm_100+ PTX, 2x fp32 throughput) --------
__device__ __forceinline__ void fma2(float2& c, const float2 a, const float2 b) {
    asm("fma.rn.f32x2 %0, %1, %2, %0;"
        : "+l"(reinterpret_cast<unsigned long long&>(c))
        : "l"(reinterpret_cast<const unsigned long long&>(a)),
          "l"(reinterpret_cast<const unsigned long long&>(b)));
}

struct __align__(16) f2x2 { float2 a, b; };   // one LDS.128 = two f32x2 operands

// ============================================================
// Kernel 1a: fc1 -> relu -> g_h.   grid(32, 8), block 256.
// ============================================================
__global__ void fc1_kernel(const float* __restrict__ x,
                           const float* __restrict__ w1, const float* __restrict__ b1)
{
    const int b = blockIdx.x, s = blockIdx.y, t = threadIdx.x;
    __shared__ __align__(16) float xs[D_];
    for (int i = t; i < D_; i += 256) xs[i] = x[b * D_ + i];
    __syncthreads();

    const int u = s * 32 + (t >> 3);
    const int l8 = t & 7;
    const float4* wr = reinterpret_cast<const float4*>(w1 + (size_t)u * D_);
    const float4* xv = reinterpret_cast<const float4*>(xs);
    float acc = 0.f;
#pragma unroll
    for (int i = 0; i < 16; i++) {
        float4 w4 = wr[l8 + 8 * i], x4 = xv[l8 + 8 * i];
        acc += w4.x * x4.x + w4.y * x4.y + w4.z * x4.z + w4.w * x4.w;
    }
#pragma unroll
    for (int o = 4; o > 0; o >>= 1) acc += __shfl_xor_sync(0xffffffffu, acc, o);
    if (l8 == 0) g_h[b * HID_ + u] = fmaxf(acc + b1[u], 0.f);
}

// ============================================================
// Kernel 1b: fc2 + softmax -> g_attn (+ tuple tail of d_out). grid(32), block 256.
// ============================================================
__global__ void fc2_kernel(const float* __restrict__ w2, const float* __restrict__ b2,
                           float* __restrict__ attn_out, int write_out)
{
    const int b = blockIdx.x, t = threadIdx.x;
    __shared__ float hs[HID_];
    __shared__ float ls[NF_];
    __shared__ float as_[NF_];
    hs[t] = g_h[b * HID_ + t];
    __syncthreads();

    const int f = t >> 5, lane = t & 31;
    float s = 0.f;
#pragma unroll
    for (int i = 0; i < HID_ / 32; i++) s += hs[lane + 32 * i] * w2[f * HID_ + lane + 32 * i];
#pragma unroll
    for (int o = 16; o > 0; o >>= 1) s += __shfl_xor_sync(0xffffffffu, s, o);
    if (lane == 0) ls[f] = s + b2[f];
    __syncthreads();

    if (t == 0) {
        float m = -1e30f;
#pragma unroll
        for (int i = 0; i < NF_; i++) m = fmaxf(m, ls[i]);
        float Z = 0.f, e[NF_];
#pragma unroll
        for (int i = 0; i < NF_; i++) { e[i] = expf((ls[i] - m) * (1.0f / 30.0f)); Z += e[i]; }
#pragma unroll
        for (int i = 0; i < NF_; i++) as_[i] = e[i] / Z;
    }
    __syncthreads();
    if (t < NF_) {
        g_attn[b * NF_ + t] = as_[t];
        if (write_out) attn_out[b * NF_ + t] = as_[t];
    }
}

// ============================================================
// Kernel 2: agg_w[b] = sum_f attn[b,f] * W[f]   (float4 streamed)
// ============================================================
__global__ void agg_kernel(const float* __restrict__ weight)
{
    const int b = blockIdx.y;
    const int e = blockIdx.x * blockDim.x + threadIdx.x;
    __shared__ float a[NF_];
    if (threadIdx.x < NF_) a[threadIdx.x] = g_attn[b * NF_ + threadIdx.x];
    __syncthreads();

    const float4* W = reinterpret_cast<const float4*>(weight);
    float4 acc = make_float4(0.f, 0.f, 0.f, 0.f);
#pragma unroll
    for (int f = 0; f < NF_; f++) {
        float4 w = W[(size_t)f * 9216 + e];
        float af = a[f];
        acc.x += af * w.x; acc.y += af * w.y; acc.z += af * w.z; acc.w += af * w.w;
    }
    reinterpret_cast<float4*>(g_aggw)[(size_t)b * 9216 + e] = acc;
}

// ============================================================
// Kernel 3: per-sample 3x3 conv, pad 1.  f32x2 over oc pairs.
// Input staged PAIR-DUPLICATED in smem (LDS.128 -> two (v,v) operands, no MOVs).
// Double-buffered CC=4 staging: stage chunk k+1 while computing chunk k.
// grid(8 tiles[32x16], 4 og, 32 b), block 256, 2 CTAs/SM.
// ============================================================
__device__ __forceinline__ void stage_chunk(
    float* __restrict__ buf, const float* __restrict__ xin,
    int cb, int tile_x, int tile_y, int t)
{
    // CC_ planes x 18 rows x 34 cols, each value written twice (pair-dup)
    for (int idx = t; idx < CC_ * 18 * 34; idx += 256) {
        int ci  = idx / (18 * 34);
        int rem = idx - ci * (18 * 34);
        int r = rem / 34;
        int c = rem - r * 34;
        int gy = tile_y - 1 + r, gx = tile_x - 1 + c;
        float v = 0.f;
        if ((unsigned)gy < (unsigned)HW_ && (unsigned)gx < (unsigned)HW_)
            v = __ldg(&xin[(size_t)(cb + ci) * (HW_ * HW_) + gy * HW_ + gx]);
        *reinterpret_cast<float2*>(&buf[(ci * 18 + r) * ISTR2_ + 2 * c]) =
            make_float2(v, v);
    }
}

__global__ void __launch_bounds__(256, 2)
conv_kernel(const float* __restrict__ x, const float* __restrict__ bias_p,
            float* __restrict__ out)
{
    extern __shared__ float smem[];
    float* w_s = smem;                        // [ci*9+tap][oc16], stride 16
    float* ib0 = smem + W_S_FLOATS;
    float* ib1 = ib0 + IN_BUF_FLOATS;

    const int b    = blockIdx.z;
    const int og   = blockIdx.y;               // 0..3
    const int tile = blockIdx.x;               // 0..7
    const int tile_y = (tile >> 1) * TH_;
    const int tile_x = (tile & 1) * TW_;
    const int t   = threadIdx.x;
    const int oh  = t >> 7;                    // 0..1 (oc half: 8 ch = 4 pairs)
    const int pt  = t & 127;
    const int row = pt >> 3;                   // 0..15
    const int x0  = (pt & 7) * 4;              // 0..28

    // prologue: transpose 16-oc weight slice into [tap-major][oc] smem
    {
        const float* wg = g_aggw + ((size_t)b * COUT_ + og * OG_) * (CIN_ * 9);
        for (int idx = t; idx < OG_ * CIN_ * 9; idx += 256) {
            int oc16 = idx / (CIN_ * 9);
            int r    = idx - oc16 * (CIN_ * 9);   // ci*9 + tap
            w_s[r * WSTR_ + oc16] = wg[(size_t)oc16 * (CIN_ * 9) + r];
        }
    }

    float2 acc[4][4];                          // [oc-pair][px]
#pragma unroll
    for (int p = 0; p < 4; p++)
#pragma unroll
        for (int j = 0; j < 4; j++) acc[p][j] = make_float2(0.f, 0.f);

    const float* xin = x + (size_t)b * CIN_ * HW_ * HW_;

    stage_chunk(ib0, xin, 0, tile_x, tile_y, t);
    __syncthreads();   // covers w_s + first chunk

    for (int ch = 0; ch < NCHUNK; ch++) {
        float* cur = (ch & 1) ? ib1 : ib0;
        float* nxt = (ch & 1) ? ib0 : ib1;
        if (ch + 1 < NCHUNK)
            stage_chunk(nxt, xin, (ch + 1) * CC_, tile_x, tile_y, t);

        const int cb = ch * CC_;
        const float* ibase = cur + row * ISTR2_ + 2 * x0;
        const float* wbase = w_s + (size_t)cb * 9 * WSTR_ + oh * 8;
#pragma unroll
        for (int ci = 0; ci < CC_; ci++) {
            const float* ib = ibase + ci * 18 * ISTR2_;
            const float* wc = wbase + ci * 9 * WSTR_;
#pragma unroll
            for (int ky = 0; ky < 3; ky++) {
                // duplicated input row: 6 pairs via 3 LDS.128
                const f2x2* ip = reinterpret_cast<const f2x2*>(ib + ky * ISTR2_);
                f2x2 i0 = ip[0], i1 = ip[1], i2 = ip[2];
                float2 dd[6] = { i0.a, i0.b, i1.a, i1.b, i2.a, i2.b };
#pragma unroll
                for (int kx = 0; kx < 3; kx++) {
                    const f2x2* wp = reinterpret_cast<const f2x2*>(
                        wc + (ky * 3 + kx) * WSTR_);
                    f2x2 wA = wp[0];   // oc pairs 0,1 (broadcast LDS.128)
                    f2x2 wB = wp[1];   // oc pairs 2,3
#pragma unroll
                    for (int j = 0; j < 4; j++) {
                        const float2 iv = dd[j + kx];
                        fma2(acc[0][j], wA.a, iv);
                        fma2(acc[1][j], wA.b, iv);
                        fma2(acc[2][j], wB.a, iv);
                        fma2(acc[3][j], wB.b, iv);
                    }
                }
            }
        }
        __syncthreads();   // staging of nxt done + cur free for overwrite
    }

    // epilogue: bias[b,oc] = sum_f attn[b,f] * bias_p[f,oc]; float4 stores
    float at[NF_];
#pragma unroll
    for (int f = 0; f < NF_; f++) at[f] = g_attn[b * NF_ + f];
    const int gx0 = tile_x + x0, gy0 = tile_y + row;
#pragma unroll
    for (int p = 0; p < 4; p++) {
        const int oc = og * OG_ + oh * 8 + 2 * p;
        float ba = 0.f, bb = 0.f;
#pragma unroll
        for (int f = 0; f < NF_; f++) {
            ba += at[f] * bias_p[f * COUT_ + oc];
            bb += at[f] * bias_p[f * COUT_ + oc + 1];
        }
        float* opa = out + (((size_t)b * COUT_ + oc) * HW_ + gy0) * HW_ + gx0;
        float* opb = opa + (size_t)HW_ * HW_;
        *reinterpret_cast<float4*>(opa) =
            make_float4(acc[p][0].x + ba, acc[p][1].x + ba, acc[p][2].x + ba, acc[p][3].x + ba);
        *reinterpret_cast<float4*>(opb) =
            make_float4(acc[p][0].y + bb, acc[p][1].y + bb, acc[p][2].y + bb, acc[p][3].y + bb);
    }
}

// ============================================================
extern "C" void kernel_launch(void* const* d_in, const int* in_sizes, int n_in,
                              void* d_out, int out_size)
{
    const float* fc_in    = (const float*)d_in[0];  // [B, D]
    const float* model_in = (const float*)d_in[1];  // [B, CIN, HW, HW]
    const float* fc1_w    = (const float*)d_in[2];  // [HID, D]
    const float* fc1_b    = (const float*)d_in[3];  // [HID]
    const float* fc2_w    = (const float*)d_in[4];  // [NF, HID]
    const float* fc2_b    = (const float*)d_in[5];  // [NF]
    const float* weight   = (const float*)d_in[6];  // [NF, COUT, CIN, 3, 3]
    const float* bias_p   = (const float*)d_in[7];  // [NF, COUT]
    float* out = (float*)d_out;

    const int conv_elems = B_ * COUT_ * HW_ * HW_;        // 8388608
    const int attn_elems = B_ * NF_;                       // 256
    int write_attn = (out_size >= conv_elems + attn_elems) ? 1 : 0;
    float* attn_out = write_attn ? (out + conv_elems) : out;

    fc1_kernel<<<dim3(B_, 8), 256>>>(fc_in, fc1_w, fc1_b);
    fc2_kernel<<<B_, 256>>>(fc2_w, fc2_b, attn_out, write_attn);
    agg_kernel<<<dim3(36, B_), 256>>>(weight);

    const size_t smem_bytes = (size_t)SMEM_FLOATS * sizeof(float);  // 78336
    cudaFuncSetAttribute(conv_kernel, cudaFuncAttributeMaxDynamicSharedMemorySize,
                         (int)smem_bytes);
    conv_kernel<<<dim3(8, 4, B_), 256, smem_bytes>>>(model_in, bias_p, out);
}

// round 11
// speedup vs baseline: 1.1473x; 1.1473x over previous
#include <cuda_runtime.h>
#include <cuda_bf16.h>

// Shapes (fixed by the problem)
#define B_   32
#define D_   512
#define HID_ 256
#define NF_  8
#define CIN_ 64
#define COUT_ 64
#define HW_  64

// Conv tiling: block = 16 oc x (32w x 16h) tile, 256 threads, 2 CTAs/SM.
// f32x2 lanes = (even ci, odd ci) partial sums -> summed in epilogue.
#define OG_    16               // output channels per block
#define TW_    32               // tile width
#define TH_    16               // tile height
#define CP_    4                // ci-PAIRS per staged chunk (8 ci)
#define NCH_   (CIN_ / (2 * CP_))   // 8 chunks
#define ISTR2_ 72               // input row stride (34 col-pairs = 68 used, pad 72)
#define WROW_  36               // weight row stride per (cp,tap): 16 oc x 2 + pad

#define W_S_FLOATS    (32 * 9 * WROW_)        // 10368
#define IN_BUF_FLOATS (CP_ * 18 * ISTR2_)     // 5184
#define SMEM_FLOATS   (W_S_FLOATS + 2 * IN_BUF_FLOATS)  // 20736 -> 82944 B

// -------- device scratch (no allocations allowed) --------
__device__ float g_attn[B_ * NF_];
__device__ float g_h[B_ * HID_];
__device__ float g_aggw[B_ * COUT_ * CIN_ * 9];  // [b][oc][ci][tap], 4.7 MB

// -------- packed fp32x2 FMA (sm_100+ PTX) --------
__device__ __forceinline__ void fma2(float2& c, const float2 a, const float2 b) {
    asm("fma.rn.f32x2 %0, %1, %2, %0;"
        : "+l"(reinterpret_cast<unsigned long long&>(c))
        : "l"(reinterpret_cast<const unsigned long long&>(a)),
          "l"(reinterpret_cast<const unsigned long long&>(b)));
}

struct __align__(16) f2x2 { float2 a, b; };   // one LDS.128 = two f32x2 operands

// ============================================================
// Kernel 1a: fc1 -> relu -> g_h.   grid(32, 8), block 256.
// ============================================================
__global__ void fc1_kernel(const float* __restrict__ x,
                           const float* __restrict__ w1, const float* __restrict__ b1)
{
    const int b = blockIdx.x, s = blockIdx.y, t = threadIdx.x;
    __shared__ __align__(16) float xs[D_];
    for (int i = t; i < D_; i += 256) xs[i] = x[b * D_ + i];
    __syncthreads();

    const int u = s * 32 + (t >> 3);
    const int l8 = t & 7;
    const float4* wr = reinterpret_cast<const float4*>(w1 + (size_t)u * D_);
    const float4* xv = reinterpret_cast<const float4*>(xs);
    float acc = 0.f;
#pragma unroll
    for (int i = 0; i < 16; i++) {
        float4 w4 = wr[l8 + 8 * i], x4 = xv[l8 + 8 * i];
        acc += w4.x * x4.x + w4.y * x4.y + w4.z * x4.z + w4.w * x4.w;
    }
#pragma unroll
    for (int o = 4; o > 0; o >>= 1) acc += __shfl_xor_sync(0xffffffffu, acc, o);
    if (l8 == 0) g_h[b * HID_ + u] = fmaxf(acc + b1[u], 0.f);
}

// ============================================================
// Kernel 1b: fc2 + softmax -> g_attn (+ tuple tail of d_out). grid(32), block 256.
// ============================================================
__global__ void fc2_kernel(const float* __restrict__ w2, const float* __restrict__ b2,
                           float* __restrict__ attn_out, int write_out)
{
    const int b = blockIdx.x, t = threadIdx.x;
    __shared__ float hs[HID_];
    __shared__ float ls[NF_];
    __shared__ float as_[NF_];
    hs[t] = g_h[b * HID_ + t];
    __syncthreads();

    const int f = t >> 5, lane = t & 31;
    float s = 0.f;
#pragma unroll
    for (int i = 0; i < HID_ / 32; i++) s += hs[lane + 32 * i] * w2[f * HID_ + lane + 32 * i];
#pragma unroll
    for (int o = 16; o > 0; o >>= 1) s += __shfl_xor_sync(0xffffffffu, s, o);
    if (lane == 0) ls[f] = s + b2[f];
    __syncthreads();

    if (t == 0) {
        float m = -1e30f;
#pragma unroll
        for (int i = 0; i < NF_; i++) m = fmaxf(m, ls[i]);
        float Z = 0.f, e[NF_];
#pragma unroll
        for (int i = 0; i < NF_; i++) { e[i] = expf((ls[i] - m) * (1.0f / 30.0f)); Z += e[i]; }
#pragma unroll
        for (int i = 0; i < NF_; i++) as_[i] = e[i] / Z;
    }
    __syncthreads();
    if (t < NF_) {
        g_attn[b * NF_ + t] = as_[t];
        if (write_out) attn_out[b * NF_ + t] = as_[t];
    }
}

// ============================================================
// Kernel 2: agg_w[b] = sum_f attn[b,f] * W[f]   (float4 streamed)
// ============================================================
__global__ void agg_kernel(const float* __restrict__ weight)
{
    const int b = blockIdx.y;
    const int e = blockIdx.x * blockDim.x + threadIdx.x;
    __shared__ float a[NF_];
    if (threadIdx.x < NF_) a[threadIdx.x] = g_attn[b * NF_ + threadIdx.x];
    __syncthreads();

    const float4* W = reinterpret_cast<const float4*>(weight);
    float4 acc = make_float4(0.f, 0.f, 0.f, 0.f);
#pragma unroll
    for (int f = 0; f < NF_; f++) {
        float4 w = W[(size_t)f * 9216 + e];
        float af = a[f];
        acc.x += af * w.x; acc.y += af * w.y; acc.z += af * w.z; acc.w += af * w.w;
    }
    reinterpret_cast<float4*>(g_aggw)[(size_t)b * 9216 + e] = acc;
}

// ============================================================
// Kernel 3 staging: CP_ ci-pairs, 18 rows x 34 cols, channel-interleaved float2.
// ============================================================
__device__ __forceinline__ void stage_chunk(
    float* __restrict__ buf, const float* __restrict__ xin,
    int cpb, int tile_x, int tile_y, int t)
{
    for (int idx = t; idx < CP_ * 18 * 34; idx += 256) {
        int cp  = idx / 612;              // 612 = 18*34
        int rem = idx - cp * 612;
        int r = rem / 34;
        int c = rem - r * 34;
        int gy = tile_y - 1 + r, gx = tile_x - 1 + c;
        float v0 = 0.f, v1 = 0.f;
        if ((unsigned)gy < (unsigned)HW_ && (unsigned)gx < (unsigned)HW_) {
            const float* p = xin + (size_t)(cpb + cp) * 2 * (HW_ * HW_) + gy * HW_ + gx;
            v0 = __ldg(p);
            v1 = __ldg(p + HW_ * HW_);
        }
        *reinterpret_cast<float2*>(&buf[(cp * 18 + r) * ISTR2_ + 2 * c]) =
            make_float2(v0, v1);
    }
}

// ============================================================
// Kernel 3: per-sample 3x3 conv, pad 1. f32x2 over (even ci, odd ci).
// grid(8 tiles[32x16], 4 og, 32 b), block 256, 2 CTAs/SM.
// thread: oh = t>>7 (8 oc), row = (t&127)>>3, x0 = (t&7)*4 (4 px).
// ============================================================
__global__ void __launch_bounds__(256, 2)
conv_kernel(const float* __restrict__ x, const float* __restrict__ bias_p,
            float* __restrict__ out)
{
    extern __shared__ float smem[];
    float* w_s = smem;                       // [cp32][tap9][oc16][2], row stride WROW_
    float* ib0 = smem + W_S_FLOATS;
    float* ib1 = ib0 + IN_BUF_FLOATS;

    const int b    = blockIdx.z;
    const int og   = blockIdx.y;               // 0..3
    const int tile = blockIdx.x;               // 0..7
    const int tile_y = (tile >> 1) * TH_;
    const int tile_x = (tile & 1) * TW_;
    const int t   = threadIdx.x;
    const int oh  = t >> 7;                    // 0..1 (8 oc each)
    const int pt  = t & 127;
    const int row = pt >> 3;                   // 0..15
    const int x0  = (pt & 7) * 4;              // 0..28

    // prologue: weight slice -> [cp][tap][oc][2] smem (coalesced STS, scattered LDG)
    {
        const float* wg = g_aggw + ((size_t)b * COUT_ + og * OG_) * (CIN_ * 9);
        for (int idx = t; idx < 32 * 9 * 32; idx += 256) {
            // idx within packed [cp][tap][oc][2] (no pad): decompose
            int p    = idx & 1;
            int oc   = (idx >> 1) & 15;
            int tc   = idx >> 5;               // cp*9 + tap
            int cp   = tc / 9;
            int tap  = tc - cp * 9;
            w_s[tc * WROW_ + oc * 2 + p] =
                wg[(size_t)oc * (CIN_ * 9) + (2 * cp + p) * 9 + tap];
        }
    }

    float2 acc[8][4];                          // [oc][px], .x even ci / .y odd ci
#pragma unroll
    for (int o = 0; o < 8; o++)
#pragma unroll
        for (int j = 0; j < 4; j++) acc[o][j] = make_float2(0.f, 0.f);

    const float* xin = x + (size_t)b * CIN_ * HW_ * HW_;

    stage_chunk(ib0, xin, 0, tile_x, tile_y, t);
    __syncthreads();   // covers w_s + first chunk

    for (int ch = 0; ch < NCH_; ch++) {
        float* cur = (ch & 1) ? ib1 : ib0;
        float* nxt = (ch & 1) ? ib0 : ib1;
        if (ch + 1 < NCH_)
            stage_chunk(nxt, xin, (ch + 1) * CP_, tile_x, tile_y, t);

        const float* wch = w_s + (size_t)ch * (CP_ * 9) * WROW_ + oh * 16;
#pragma unroll
        for (int cp = 0; cp < CP_; cp++) {
            const float* ib = cur + (cp * 18 + row) * ISTR2_ + 2 * x0;
            const float* wc = wch + cp * 9 * WROW_;
#pragma unroll
            for (int ky = 0; ky < 3; ky++) {
                // 6 col-pairs via 3 LDS.128 (channel-interleaved, no packing MOVs)
                const f2x2* ip = reinterpret_cast<const f2x2*>(ib + ky * ISTR2_);
                f2x2 iA = ip[0], iB = ip[1], iC = ip[2];
                float2 iv[6] = { iA.a, iA.b, iB.a, iB.b, iC.a, iC.b };
#pragma unroll
                for (int kx = 0; kx < 3; kx++) {
                    // 8 oc weight pairs for this tap: 4 broadcast LDS.128
                    const f2x2* wp = reinterpret_cast<const f2x2*>(
                        wc + (ky * 3 + kx) * WROW_);
                    f2x2 w01 = wp[0], w23 = wp[1], w45 = wp[2], w67 = wp[3];
#pragma unroll
                    for (int j = 0; j < 4; j++) {
                        const float2 ix = iv[j + kx];
                        fma2(acc[0][j], w01.a, ix);
                        fma2(acc[1][j], w01.b, ix);
                        fma2(acc[2][j], w23.a, ix);
                        fma2(acc[3][j], w23.b, ix);
                        fma2(acc[4][j], w45.a, ix);
                        fma2(acc[5][j], w45.b, ix);
                        fma2(acc[6][j], w67.a, ix);
                        fma2(acc[7][j], w67.b, ix);
                    }
                }
            }
        }
        __syncthreads();   // nxt staged + cur free
    }

    // epilogue: combine even/odd halves + dynamic bias; float4 stores
    float at[NF_];
#pragma unroll
    for (int f = 0; f < NF_; f++) at[f] = g_attn[b * NF_ + f];
    const int gx0 = tile_x + x0, gy0 = tile_y + row;
#pragma unroll
    for (int o = 0; o < 8; o++) {
        const int oc = og * OG_ + oh * 8 + o;
        float bias = 0.f;
#pragma unroll
        for (int f = 0; f < NF_; f++) bias += at[f] * bias_p[f * COUT_ + oc];
        float* op = out + (((size_t)b * COUT_ + oc) * HW_ + gy0) * HW_ + gx0;
        *reinterpret_cast<float4*>(op) = make_float4(
            acc[o][0].x + acc[o][0].y + bias,
            acc[o][1].x + acc[o][1].y + bias,
            acc[o][2].x + acc[o][2].y + bias,
            acc[o][3].x + acc[o][3].y + bias);
    }
}

// ============================================================
extern "C" void kernel_launch(void* const* d_in, const int* in_sizes, int n_in,
                              void* d_out, int out_size)
{
    const float* fc_in    = (const float*)d_in[0];  // [B, D]
    const float* model_in = (const float*)d_in[1];  // [B, CIN, HW, HW]
    const float* fc1_w    = (const float*)d_in[2];  // [HID, D]
    const float* fc1_b    = (const float*)d_in[3];  // [HID]
    const float* fc2_w    = (const float*)d_in[4];  // [NF, HID]
    const float* fc2_b    = (const float*)d_in[5];  // [NF]
    const float* weight   = (const float*)d_in[6];  // [NF, COUT, CIN, 3, 3]
    const float* bias_p   = (const float*)d_in[7];  // [NF, COUT]
    float* out = (float*)d_out;

    const int conv_elems = B_ * COUT_ * HW_ * HW_;        // 8388608
    const int attn_elems = B_ * NF_;                       // 256
    int write_attn = (out_size >= conv_elems + attn_elems) ? 1 : 0;
    float* attn_out = write_attn ? (out + conv_elems) : out;

    fc1_kernel<<<dim3(B_, 8), 256>>>(fc_in, fc1_w, fc1_b);
    fc2_kernel<<<B_, 256>>>(fc2_w, fc2_b, attn_out, write_attn);
    agg_kernel<<<dim3(36, B_), 256>>>(weight);

    const size_t smem_bytes = (size_t)SMEM_FLOATS * sizeof(float);  // 82944
    cudaFuncSetAttribute(conv_kernel, cudaFuncAttributeMaxDynamicSharedMemorySize,
                         (int)smem_bytes);
    conv_kernel<<<dim3(8, 4, B_), 256, smem_bytes>>>(model_in, bias_p, out);
}